// round 8
// baseline (speedup 1.0000x reference)
#include <cuda_runtime.h>
#include <stdint.h>

// Fixed shapes: b=128 planes of 128 channels? No: b=128 batch, C=128.
// x: [128,128,56,56] f32, out: [128,128,58,58] f32.
#define CC      128
#define HH      56
#define WW      56
#define OH      58
#define OW      58
#define PLANE   (OH * OW)     // 3364
#define IPLANE  (HH * WW)     // 3136
#define VECPP   (PLANE / 4)   // 841 vec4 groups per (bi,c) plane
#define NPLANES (128u * 128u) // 16384

__global__ __launch_bounds__(128)
void pad2d_kernel(const float* __restrict__ x,
                  const float* __restrict__ topW,
                  const float* __restrict__ botW,
                  const float* __restrict__ leftW,
                  const float* __restrict__ rightW,
                  const float* __restrict__ tlW,
                  const float* __restrict__ trW,
                  const float* __restrict__ blW,
                  const float* __restrict__ brW,
                  float4* __restrict__ out)
{
    unsigned g = blockIdx.x * blockDim.x + threadIdx.x;   // vec4 index in plane
    if (g >= VECPP) return;
    unsigned plane = blockIdx.y;                          // 0..16383

    unsigned t0   = g * 4u;                               // 0..3360
    unsigned row0 = t0 / (unsigned)OW;                    // single const-div
    unsigned col0 = t0 - row0 * (unsigned)OW;

    const float* xp = x + (size_t)plane * IPLANE;
    float4 o;

    if (row0 >= 1u && row0 <= HH && col0 >= 1u && col0 <= (WW - 3u)) {
        // Fast path: 4 consecutive interior elements in one row.
        const float* p = xp + (row0 - 1u) * WW + (col0 - 1u);
        o = make_float4(p[0], p[1], p[2], p[3]);
    } else {
        // General path (boundary / row-straddling groups only).
        unsigned c  = plane & (CC - 1);
        unsigned bi = plane >> 7;
        unsigned within = bi & 3u;       // num_patches=2 -> P*P=4
        bool top_m   = within < 2u;
        bool bot_m   = within >= 2u;
        bool left_m  = (bi & 1u) == 0u;
        bool right_m = (bi & 1u) == 1u;

        float v[4];
        unsigned row = row0, col = col0;
#pragma unroll
        for (int k = 0; k < 4; ++k) {
            float r;
            if (row >= 1u && row <= HH && col >= 1u && col <= WW) {
                r = xp[(row - 1u) * WW + (col - 1u)];
            } else if ((top_m && row == 0u) || (bot_m && row == OH - 1) ||
                       (left_m && col == 0u) || (right_m && col == OW - 1)) {
                r = 0.0f;
            } else if (row == 0u) {
                if (col == 0u)           r = tlW[c] * xp[0];
                else if (col == OW - 1)  r = trW[c] * xp[WW - 1];
                else                     r = topW[c] * (xp[col - 1u] + xp[WW + col - 1u]);
            } else if (row == OH - 1) {
                if (col == 0u)           r = blW[c] * xp[(HH - 1) * WW];
                else if (col == OW - 1)  r = brW[c] * xp[(HH - 1) * WW + WW - 1];
                else                     r = botW[c] * (xp[(HH - 2) * WW + col - 1u] +
                                                        xp[(HH - 1) * WW + col - 1u]);
            } else if (col == 0u) {
                r = leftW[c] * (xp[(row - 1u) * WW] + xp[(row - 1u) * WW + 1u]);
            } else { // col == OW-1
                r = rightW[c] * (xp[(row - 1u) * WW + WW - 2u] +
                                 xp[(row - 1u) * WW + WW - 1u]);
            }
            v[k] = r;
            if (++col == (unsigned)OW) { col = 0u; ++row; }
        }
        o = make_float4(v[0], v[1], v[2], v[3]);
    }

    out[(size_t)plane * VECPP + g] = o;
}

extern "C" void kernel_launch(void* const* d_in, const int* in_sizes, int n_in,
                              void* d_out, int out_size)
{
    const float* x      = (const float*)d_in[0];
    const float* topW   = (const float*)d_in[1];
    const float* botW   = (const float*)d_in[2];
    const float* leftW  = (const float*)d_in[3];
    const float* rightW = (const float*)d_in[4];
    const float* tlW    = (const float*)d_in[5];
    const float* trW    = (const float*)d_in[6];
    const float* blW    = (const float*)d_in[7];
    const float* brW    = (const float*)d_in[8];
    // d_in[9] = padding (==1), d_in[10] = num_patches (==2): baked in.

    dim3 grid((VECPP + 127) / 128, NPLANES, 1);   // (7, 16384)
    pad2d_kernel<<<grid, 128>>>(x, topW, botW, leftW, rightW,
                                tlW, trW, blW, brW, (float4*)d_out);
}